// round 2
// baseline (speedup 1.0000x reference)
#include <cuda_runtime.h>

// Problem constants
#define BB   4
#define HH   8
#define LL   1024
#define DD   64
#define VV   1027          // 2*513+1 relative positions
#define MAXREL 513
#define MTOT (BB*HH*LL)    // 32768 rows
#define SS   1028          // padded row stride for S/T scratch (16B-aligned rows)
#define OUT_ELEMS (MTOT*DD) // 2097152 ; weights follow in d_out

// Scratch: holds S = Q @ EK^T, later reused for T (weight bins). 134.7 MB.
__device__ float g_S[(size_t)MTOT * SS];

typedef unsigned long long ull;

// ---- packed f32x2 helpers (the only way to reach 128 FMA/cyc/SM on sm_103a) ----
__device__ __forceinline__ void ffma2(ull &acc, ull a, ull b) {
    asm volatile("fma.rn.f32x2 %0, %1, %2, %0;" : "+l"(acc) : "l"(a), "l"(b));
}
__device__ __forceinline__ ull bcast2(float x) {
    ull r; asm("mov.b64 %0, {%1, %1};" : "=l"(r) : "f"(x)); return r;
}
__device__ __forceinline__ float2 unpack2(ull v) {
    float2 f; asm("mov.b64 {%0, %1}, %2;" : "=f"(f.x), "=f"(f.y) : "l"(v)); return f;
}

// ---- shared inner MMA: block tile 128(m) x 64(n), K-tile 64, 128 threads, 8x8/thread ----
// As: [m][k] = [128][64] (k contiguous). Bs: [k][n] = [64][64] (n contiguous).
__device__ __forceinline__ void mma_tile(const float* __restrict__ As,
                                         const float* __restrict__ Bs,
                                         ull (&acc)[8][4], int row0, int col0) {
#pragma unroll 4
    for (int k4 = 0; k4 < 16; ++k4) {
        float4 a[8];
#pragma unroll
        for (int r = 0; r < 8; ++r)
            a[r] = *reinterpret_cast<const float4*>(&As[(row0 + r) * 64 + k4 * 4]);
#pragma unroll
        for (int u = 0; u < 4; ++u) {
            const int kk = k4 * 4 + u;
            const ull* bp = reinterpret_cast<const ull*>(&Bs[kk * 64 + col0]);
            ull b0 = bp[0], b1 = bp[1], b2 = bp[2], b3 = bp[3];
#pragma unroll
            for (int r = 0; r < 8; ++r) {
                const float* af = reinterpret_cast<const float*>(&a[r]);
                ull ap = bcast2(af[u]);
                ffma2(acc[r][0], ap, b0);
                ffma2(acc[r][1], ap, b1);
                ffma2(acc[r][2], ap, b2);
                ffma2(acc[r][3], ap, b3);
            }
        }
    }
}

// ============================================================
// Kernel 1: S[m, j] = sum_d Q[m, d] * EK[j, d]   (M=32768, N=1027, K=64)
// ============================================================
__global__ void __launch_bounds__(128) s_gemm_kernel(const float* __restrict__ q,
                                                     const float* __restrict__ ek) {
    __shared__ float As[128 * 64];
    __shared__ float Bs[64 * 64];
    const int tid = threadIdx.x;
    const int m0 = blockIdx.x * 128;
    const int n0 = blockIdx.y * 64;

#pragma unroll
    for (int i = 0; i < 16; ++i) {                    // A: 128x64 direct
        int f = tid + i * 128;
        int m = f >> 4, kq = (f & 15) * 4;
        *reinterpret_cast<float4*>(&As[m * 64 + kq]) =
            *reinterpret_cast<const float4*>(&q[(size_t)(m0 + m) * 64 + kq]);
    }
#pragma unroll
    for (int i = 0; i < 8; ++i) {                     // B: transpose EK[n][k] -> Bs[k][n]
        int f = tid + i * 128;
        int nl = f >> 4, kq = (f & 15) * 4;
        int ng = n0 + nl;
        float4 vv = make_float4(0.f, 0.f, 0.f, 0.f);
        if (ng < VV) vv = *reinterpret_cast<const float4*>(&ek[(size_t)ng * 64 + kq]);
        Bs[(kq + 0) * 64 + nl] = vv.x;
        Bs[(kq + 1) * 64 + nl] = vv.y;
        Bs[(kq + 2) * 64 + nl] = vv.z;
        Bs[(kq + 3) * 64 + nl] = vv.w;
    }
    __syncthreads();

    const int tx = tid & 7, ty = tid >> 3;
    ull acc[8][4];
#pragma unroll
    for (int r = 0; r < 8; ++r)
#pragma unroll
        for (int p = 0; p < 4; ++p) acc[r][p] = 0ULL;

    mma_tile(As, Bs, acc, ty * 8, tx * 8);

#pragma unroll
    for (int r = 0; r < 8; ++r) {
        int row = m0 + ty * 8 + r;
        float* srow = g_S + (size_t)row * SS;
#pragma unroll
        for (int p = 0; p < 4; ++p) {
            float2 vv = unpack2(acc[r][p]);
            int c0 = n0 + tx * 8 + p * 2;
            if (c0     < VV) srow[c0]     = vv.x;
            if (c0 + 1 < VV) srow[c0 + 1] = vv.y;
        }
    }
}

// ============================================================
// Kernel 2: logits[bh, x, y] = Q.K^T + bias + S[bh*L+x, clip(y-x)+513]
// written directly into the weights output region.
// ============================================================
__global__ void __launch_bounds__(128) qk_kernel(const float* __restrict__ q,
                                                 const float* __restrict__ kmat,
                                                 const float* __restrict__ bias,
                                                 float* __restrict__ W) {
    __shared__ float As[128 * 64];
    __shared__ float Bs[64 * 64];
    const int tid = threadIdx.x;
    const int bh = blockIdx.z;
    const int m0 = blockIdx.x * 128;
    const int n0 = blockIdx.y * 64;
    const float* qb = q    + (size_t)bh * LL * DD;
    const float* kb = kmat + (size_t)bh * LL * DD;

#pragma unroll
    for (int i = 0; i < 16; ++i) {
        int f = tid + i * 128;
        int m = f >> 4, kq = (f & 15) * 4;
        *reinterpret_cast<float4*>(&As[m * 64 + kq]) =
            *reinterpret_cast<const float4*>(&qb[(size_t)(m0 + m) * 64 + kq]);
    }
#pragma unroll
    for (int i = 0; i < 8; ++i) {                     // transpose K[y][d] -> Bs[d][y]
        int f = tid + i * 128;
        int nl = f >> 4, kq = (f & 15) * 4;
        float4 vv = *reinterpret_cast<const float4*>(&kb[(size_t)(n0 + nl) * 64 + kq]);
        Bs[(kq + 0) * 64 + nl] = vv.x;
        Bs[(kq + 1) * 64 + nl] = vv.y;
        Bs[(kq + 2) * 64 + nl] = vv.z;
        Bs[(kq + 3) * 64 + nl] = vv.w;
    }
    __syncthreads();

    const int tx = tid & 7, ty = tid >> 3;
    ull acc[8][4];
#pragma unroll
    for (int r = 0; r < 8; ++r)
#pragma unroll
        for (int p = 0; p < 4; ++p) acc[r][p] = 0ULL;

    mma_tile(As, Bs, acc, ty * 8, tx * 8);

    const float* biasb = bias + (size_t)bh * LL * LL;
    float*       Wb    = W    + (size_t)bh * LL * LL;
    const float* Sb    = g_S  + (size_t)bh * LL * SS;

#pragma unroll
    for (int r = 0; r < 8; ++r) {
        int row = m0 + ty * 8 + r;
        const float* srow = Sb + (size_t)row * SS;
        const float* brow = biasb + (size_t)row * LL;
        float*       wrow = Wb    + (size_t)row * LL;
#pragma unroll
        for (int p = 0; p < 4; ++p) {
            float2 vv = unpack2(acc[r][p]);
            int c0 = n0 + tx * 8 + p * 2;
            int j0 = c0 - row;     j0 = min(max(j0, -MAXREL), MAXREL) + MAXREL;
            int j1 = c0 + 1 - row; j1 = min(max(j1, -MAXREL), MAXREL) + MAXREL;
            wrow[c0]     = vv.x + brow[c0]     + srow[j0];
            wrow[c0 + 1] = vv.y + brow[c0 + 1] + srow[j1];
        }
    }
}

// ============================================================
// Kernel 3 (fused): in-place row softmax + build T bins in one pass.
// T[m, j]: interior j=1..1025 is a single copy W[m, x + j - 513] (or 0 if
// y out of range); j=0 / j=1026 are the clipped-region sums. The zero-fill
// write-set (invalid y) and the scatter write-set (valid y) are disjoint,
// so no intra-block ordering is needed beyond the final reductions.
// ============================================================
__global__ void __launch_bounds__(256) softmax_tbuild_kernel(float* __restrict__ W) {
    const int m = blockIdx.x;
    const int rowx = m & (LL - 1);
    const int tid = threadIdx.x;
    float4* row = reinterpret_cast<float4*>(W + (size_t)m * LL);
    float* t = g_S + (size_t)m * SS;

    float4 x = row[tid];

    // --- row max ---
    float mx = fmaxf(fmaxf(x.x, x.y), fmaxf(x.z, x.w));
#pragma unroll
    for (int o = 16; o; o >>= 1) mx = fmaxf(mx, __shfl_xor_sync(0xffffffffu, mx, o));
    __shared__ float redm[8];
    __shared__ float reds[8];
    if ((tid & 31) == 0) redm[tid >> 5] = mx;
    __syncthreads();
    float m2 = redm[0];
#pragma unroll
    for (int i = 1; i < 8; ++i) m2 = fmaxf(m2, redm[i]);

    // --- exp + row sum ---
    x.x = __expf(x.x - m2);
    x.y = __expf(x.y - m2);
    x.z = __expf(x.z - m2);
    x.w = __expf(x.w - m2);
    float s = (x.x + x.y) + (x.z + x.w);
#pragma unroll
    for (int o = 16; o; o >>= 1) s += __shfl_xor_sync(0xffffffffu, s, o);
    if ((tid & 31) == 0) reds[tid >> 5] = s;
    __syncthreads();
    float st = reds[0];
#pragma unroll
    for (int i = 1; i < 8; ++i) st += reds[i];

    float inv = 1.0f / st;
    x.x *= inv; x.y *= inv; x.z *= inv; x.w *= inv;
    row[tid] = x;                       // normalized weights out

    // --- T build from in-register values ---
    // zero-fill interior bins whose source y is out of range
    for (int j = 1 + tid; j <= 1025; j += 256) {
        int y = rowx + j - MAXREL;
        if ((unsigned)y >= (unsigned)LL) t[j] = 0.f;
    }
    // scatter held values; accumulate clipped edges
    const float vals[4] = {x.x, x.y, x.z, x.w};
    float sp = 0.f, sq = 0.f;
    const int y0 = tid * 4;
#pragma unroll
    for (int u = 0; u < 4; ++u) {
        int dist = y0 + u - rowx;
        if (dist <= -MAXREL)      sp += vals[u];
        else if (dist >= MAXREL)  sq += vals[u];
        else                      t[dist + MAXREL] = vals[u];
    }
#pragma unroll
    for (int o = 16; o; o >>= 1) {
        sp += __shfl_xor_sync(0xffffffffu, sp, o);
        sq += __shfl_xor_sync(0xffffffffu, sq, o);
    }
    __shared__ float r1[8];
    __shared__ float r2[8];
    if ((tid & 31) == 0) { r1[tid >> 5] = sp; r2[tid >> 5] = sq; }
    __syncthreads();
    if (tid == 0) {
        float a = 0.f, b = 0.f;
#pragma unroll
        for (int i = 0; i < 8; ++i) { a += r1[i]; b += r2[i]; }
        t[0] = a;
        t[1026] = b;
    }
}

// ============================================================
// Kernel 4: out = W @ V + T @ EV   (M=1024 per bh, N=64, K=1024 then 1027)
// ============================================================
__global__ void __launch_bounds__(128) out_kernel(const float* __restrict__ W,
                                                  const float* __restrict__ v,
                                                  const float* __restrict__ ev,
                                                  float* __restrict__ out) {
    __shared__ float As[128 * 64];
    __shared__ float Bs[64 * 64];
    const int tid = threadIdx.x;
    const int bh = blockIdx.z;
    const int m0 = blockIdx.x * 128;
    const float* Wb = W + (size_t)bh * LL * LL;
    const float* vb = v + (size_t)bh * LL * DD;
    const size_t tbase = (size_t)(bh * LL + m0);

    const int tx = tid & 7, ty = tid >> 3;
    ull acc[8][4];
#pragma unroll
    for (int r = 0; r < 8; ++r)
#pragma unroll
        for (int p = 0; p < 4; ++p) acc[r][p] = 0ULL;

    for (int kt = 0; kt < 33; ++kt) {
        if (kt < 16) {
            const int koff = kt * 64;
#pragma unroll
            for (int i = 0; i < 16; ++i) {            // As <- W[m][koff+k] (stride 1024)
                int f = tid + i * 128;
                int mm = f >> 4, kq = (f & 15) * 4;
                *reinterpret_cast<float4*>(&As[mm * 64 + kq]) =
                    *reinterpret_cast<const float4*>(&Wb[(size_t)(m0 + mm) * LL + koff + kq]);
            }
#pragma unroll
            for (int i = 0; i < 8; ++i) {             // Bs <- V[koff+k][d] direct
                int f = tid + i * 128;
                int kl = f >> 4, nn = (f & 15) * 4;
                *reinterpret_cast<float4*>(&Bs[kl * 64 + nn]) =
                    *reinterpret_cast<const float4*>(&vb[(size_t)(koff + kl) * 64 + nn]);
            }
        } else {
            const int koff = (kt - 16) * 64;
#pragma unroll
            for (int i = 0; i < 16; ++i) {            // As <- T rows (stride SS), guarded
                int f = tid + i * 128;
                int mm = f >> 4, jq = koff + (f & 15) * 4;
                const float* tr = g_S + (tbase + mm) * SS;
                float4 vv;
                if (jq + 3 < VV) {
                    vv = *reinterpret_cast<const float4*>(&tr[jq]);
                } else {
                    vv.x = (jq     < VV) ? tr[jq]     : 0.f;
                    vv.y = (jq + 1 < VV) ? tr[jq + 1] : 0.f;
                    vv.z = (jq + 2 < VV) ? tr[jq + 2] : 0.f;
                    vv.w = (jq + 3 < VV) ? tr[jq + 3] : 0.f;
                }
                *reinterpret_cast<float4*>(&As[mm * 64 + jq - koff]) = vv;
            }
#pragma unroll
            for (int i = 0; i < 8; ++i) {             // Bs <- EV[koff+k][d], guarded
                int f = tid + i * 128;
                int kl = f >> 4, nn = (f & 15) * 4;
                int kg = koff + kl;
                float4 vv = make_float4(0.f, 0.f, 0.f, 0.f);
                if (kg < VV) vv = *reinterpret_cast<const float4*>(&ev[(size_t)kg * 64 + nn]);
                *reinterpret_cast<float4*>(&Bs[kl * 64 + nn]) = vv;
            }
        }
        __syncthreads();
        mma_tile(As, Bs, acc, ty * 8, tx * 8);
        __syncthreads();
    }

#pragma unroll
    for (int r = 0; r < 8; ++r) {
        int row = m0 + ty * 8 + r;
        float* orow = out + (size_t)(bh * LL + row) * DD;
#pragma unroll
        for (int p = 0; p < 4; ++p) {
            float2 vv = unpack2(acc[r][p]);
            int c0 = tx * 8 + p * 2;
            orow[c0]     = vv.x;
            orow[c0 + 1] = vv.y;
        }
    }
}

// ============================================================
extern "C" void kernel_launch(void* const* d_in, const int* in_sizes, int n_in,
                              void* d_out, int out_size) {
    const float* q    = (const float*)d_in[0];
    const float* k    = (const float*)d_in[1];
    const float* v    = (const float*)d_in[2];
    const float* bias = (const float*)d_in[3];
    const float* ek   = (const float*)d_in[4];
    const float* ev   = (const float*)d_in[5];
    float* out = (float*)d_out;              // (B,H,L,D) first
    float* W   = out + OUT_ELEMS;            // then weights (B,H,L,L)

    dim3 b128(128), b256(256);
    s_gemm_kernel<<<dim3(256, 17), b128>>>(q, ek);
    qk_kernel<<<dim3(8, 16, 32), b128>>>(q, k, bias, W);
    softmax_tbuild_kernel<<<MTOT, b256>>>(W);
    out_kernel<<<dim3(8, 1, 32), b128>>>(W, v, ev, out);
}